// round 14
// baseline (speedup 1.0000x reference)
#include <cuda_runtime.h>
#include <cuda_bf16.h>
#include <cstdint>

#define N_NODES 40000
#define N_EDGES 640000
#define HID 128
#define SCAN_BLOCKS 40

// ---------------- scratch (static __device__, no allocations) ----------------
__device__ float g_bufA  [N_NODES * HID];
__device__ float g_bufCat[N_NODES * 2 * HID];
__device__ int   g_cnt   [N_NODES];
__device__ int   g_rp    [N_NODES + 1];
__device__ int   g_cursor[N_NODES];
__device__ int   g_csrc  [N_EDGES];
__device__ int   g_bsum  [SCAN_BLOCKS];
// pre-split weights (bf16 hi/lo): c0w2, c1w2, combo0, combo1
#define WOFF_C0W2 0
#define WOFF_C1W2 16384
#define WOFF_CB0  32768
#define WOFF_CB1  65536
#define WTOTAL    98304
__device__ __nv_bfloat16 g_whi[WTOTAL];
__device__ __nv_bfloat16 g_wlo[WTOTAL];
__device__ float g_bc0[HID];
__device__ float g_bc1[HID];

// ---------------- fused: lin_in (blocks 0..2499) + hist (2500..4999) ----------
__global__ __launch_bounds__(256)
void k_lin_hist(const float* __restrict__ x, const float* __restrict__ w1,
                const float* __restrict__ b1, float* __restrict__ out,
                const int* __restrict__ dst) {
    if (blockIdx.x < 2500) {
        __shared__ float xs[16 * 11];
        const int tid = threadIdx.x;
        const int col = tid & 127, half = tid >> 7;
        float wr[11];
#pragma unroll
        for (int k = 0; k < 11; k++) wr[k] = w1[col * 11 + k];
        const float bb = b1[col];
        const int row0 = blockIdx.x * 16;
        for (int i = tid; i < 16 * 11; i += 256) xs[i] = x[row0 * 11 + i];
        __syncthreads();
#pragma unroll
        for (int rr = 0; rr < 8; rr++) {
            const int r = half * 8 + rr;
            float acc = bb;
#pragma unroll
            for (int k = 0; k < 11; k++) acc += xs[r * 11 + k] * wr[k];
            out[(size_t)(row0 + r) * HID + col] = fmaxf(acc, 0.f);
        }
    } else {
        int e = (blockIdx.x - 2500) * 256 + threadIdx.x;
        if (e < N_EDGES) atomicAdd(&g_cnt[dst[e]], 1);
    }
}

// ---------------- 2-phase parallel scan ----------------
__global__ __launch_bounds__(1024)
void k_scan1() {
    __shared__ int warpsum[32];
    const int tid = threadIdx.x;
    const int lane = tid & 31, wid = tid >> 5;
    const int i = blockIdx.x * 1024 + tid;
    int v = (i < N_NODES) ? g_cnt[i] : 0;
    int s = v;
#pragma unroll
    for (int o = 1; o < 32; o <<= 1) {
        int t = __shfl_up_sync(0xffffffffu, s, o);
        if (lane >= o) s += t;
    }
    if (lane == 31) warpsum[wid] = s;
    __syncthreads();
    if (wid == 0) {
        int w = warpsum[lane];
#pragma unroll
        for (int o = 1; o < 32; o <<= 1) {
            int t = __shfl_up_sync(0xffffffffu, w, o);
            if (lane >= o) w += t;
        }
        warpsum[lane] = w;
    }
    __syncthreads();
    int incl = s + (wid ? warpsum[wid - 1] : 0);
    if (i < N_NODES) g_rp[i] = incl - v;
    if (tid == 1023) g_bsum[blockIdx.x] = incl;
}

__global__ __launch_bounds__(1024)
void k_scan23() {
    __shared__ int boff;
    __shared__ int total;
    if (threadIdx.x == 0) {
        int run = 0, mine = 0;
        for (int b = 0; b < SCAN_BLOCKS; b++) {
            if (b == (int)blockIdx.x) mine = run;
            run += g_bsum[b];
        }
        boff = mine;
        total = run;
    }
    __syncthreads();
    const int i = blockIdx.x * 1024 + threadIdx.x;
    if (i < N_NODES) {
        int v = g_rp[i] + boff;
        g_rp[i] = v;
        g_cursor[i] = v;
    }
    if (blockIdx.x == 0 && threadIdx.x == 0) g_rp[N_NODES] = total;
}

__global__ void k_fill(const int* __restrict__ src, const int* __restrict__ dst) {
    int e = blockIdx.x * blockDim.x + threadIdx.x;
    if (e < N_EDGES) {
        int p = atomicAdd(&g_cursor[dst[e]], 1);
        g_csrc[p] = src[e];
    }
}

// ---------------- weight pre-split (+ g_cnt zeroing) ----------------
__global__ void k_wsplit(const float* __restrict__ s0, const float* __restrict__ s1) {
    int i = blockIdx.x * 256 + threadIdx.x;
    if (i < N_NODES) g_cnt[i] = 0;
    if (i >= 32768) return;
    float v = (i < 16384) ? s0[i] : s1[i - 16384];
    __nv_bfloat16 h = __float2bfloat16_rn(v);
    g_whi[i] = h;
    g_wlo[i] = __float2bfloat16_rn(v - __bfloat162float(h));
}

// ---------------- combo precompute ----------------
__global__ __launch_bounds__(256)
void k_combo(const float* __restrict__ c1w1, const float* __restrict__ c0w3,
             const float* __restrict__ c0b3, const float* __restrict__ c1b1,
             const float* __restrict__ fw1,  const float* __restrict__ c1w3,
             const float* __restrict__ c1b3, const float* __restrict__ fb1) {
    __shared__ float wrow[128];
    const int c = blockIdx.x >> 7;
    const int i = blockIdx.x & 127;
    const int j = threadIdx.x;
    const float* w1 = c ? fw1 : c1w1;
    const float* w3 = c ? c1w3 : c0w3;
    const float* b3 = c ? c1b3 : c0b3;
    const float* b1 = c ? fb1 : c1b1;
    if (j < 128) wrow[j] = w1[i * 128 + j];
    __syncthreads();
    float acc = 0.f;
#pragma unroll 8
    for (int k = 0; k < 128; k++) acc += wrow[k] * w3[k * 256 + j];
    const int off = (c ? WOFF_CB1 : WOFF_CB0) + i * 256 + j;
    __nv_bfloat16 h = __float2bfloat16_rn(acc);
    g_whi[off] = h;
    g_wlo[off] = __float2bfloat16_rn(acc - __bfloat162float(h));
    if (j == 0) {
        float s = 0.f;
        for (int k = 0; k < 128; k++) s += wrow[k] * b3[k];
        (c ? g_bc1 : g_bc0)[i] = s + b1[i];
    }
}

// ---------------- common MMA helpers ----------------
__device__ __forceinline__ uint32_t smem_u32(const void* p) {
    uint32_t a;
    asm("{ .reg .u64 t; cvta.to.shared.u64 t, %1; cvt.u32.u64 %0, t; }"
        : "=r"(a) : "l"(p));
    return a;
}
__device__ __forceinline__ void mma_bf16(float d[4], const uint32_t a[4],
                                         const uint32_t b[2]) {
    asm volatile(
        "mma.sync.aligned.m16n8k16.row.col.f32.bf16.bf16.f32 "
        "{%0,%1,%2,%3}, {%4,%5,%6,%7}, {%8,%9}, {%0,%1,%2,%3};"
        : "+f"(d[0]), "+f"(d[1]), "+f"(d[2]), "+f"(d[3])
        : "r"(a[0]), "r"(a[1]), "r"(a[2]), "r"(a[3]), "r"(b[0]), "r"(b[1]));
}
#define LDMX4(r, addr) \
    asm volatile("ldmatrix.sync.aligned.m8n8.x4.shared.b16 {%0,%1,%2,%3}, [%4];" \
                 : "=r"((r)[0]), "=r"((r)[1]), "=r"((r)[2]), "=r"((r)[3]) : "r"(addr))
#define LDMX2(r, addr) \
    asm volatile("ldmatrix.sync.aligned.m8n8.x2.shared.b16 {%0,%1}, [%2];" \
                 : "=r"((r)[0]), "=r"((r)[1]) : "r"(addr))

__device__ __forceinline__ uint32_t pack_hi(float x, float y, float& lx, float& ly) {
    __nv_bfloat162 h = __floats2bfloat162_rn(x, y);
    lx = x - __bfloat162float(h.x);
    ly = y - __bfloat162float(h.y);
    return *(uint32_t*)&h;
}
__device__ __forceinline__ uint32_t pack_bf2(float x, float y) {
    __nv_bfloat162 h = __floats2bfloat162_rn(x, y);
    return *(uint32_t*)&h;
}

// ============= fused spmm+GEMM: C = relu((A_gather) @ W^T + b), K=128 =========
// dynamic SMEM: Ahi 8 stages x 3072 = 24576, Alo 24576, W dbuf 2 x 12288
#define FA_HI 0
#define FA_LO 24576
#define FW    49152
#define FW_SZ 12288
#define F_SMEM 73728

__global__ __launch_bounds__(256, 2)
void k_spgemm(const float* __restrict__ h, int lda,
              const __nv_bfloat16* __restrict__ Whi,
              const __nv_bfloat16* __restrict__ Wlo,
              const float* __restrict__ bias,
              float* __restrict__ C, int ldc) {
    extern __shared__ __align__(16) char dsm[];
    const uint32_t sb = smem_u32(dsm);

    const int tid = threadIdx.x, warp = tid >> 5, lane = tid & 31;
    const int wr = warp >> 2, wc = warp & 3;
    const int row0 = blockIdx.x * 64;

    // W loader coords (K=128 fixed)
    const int wn = tid >> 1, whalf = tid & 1;
    const __nv_bfloat16* whptr = Whi + (size_t)wn * 128 + 8 * whalf;
    const __nv_bfloat16* wlptr = Wlo + (size_t)wn * 128 + 8 * whalf;
    const uint32_t wDst = (uint32_t)(wn * 48 + 16 * whalf);

    const uint32_t a_lo = (uint32_t)(((wr * 32) + (lane & 7) + ((lane >> 3) & 1) * 8) * 48
                                     + ((lane >> 4) * 16));
    const uint32_t b_lo = (uint32_t)(((wc * 32) + (lane & 7)) * 48 + ((lane >> 3) & 1) * 16);

    // prefetch W stage 0 (overlaps gather)
    uint4 pwh = *(const uint4*)whptr;
    uint4 pwl = *(const uint4*)wlptr;

    // ---- phase 1: gather-sum 8 rows per warp, split to bf16 hi/lo in SMEM ----
    const int off = lane << 2;
    const uint32_t stg = (uint32_t)(lane >> 2), aq = (uint32_t)(lane & 3);
#pragma unroll 1
    for (int rr = 0; rr < 8; rr++) {
        const int rloc = warp * 8 + rr;
        const int node = row0 + rloc;
        const int beg = g_rp[node], end = g_rp[node + 1];
        float4 acc = make_float4(0.f, 0.f, 0.f, 0.f);
        int e = beg;
        for (; e + 7 < end; e += 8) {
            int sx[8];
#pragma unroll
            for (int j = 0; j < 8; j++) sx[j] = g_csrc[e + j];
            float4 v[8];
#pragma unroll
            for (int j = 0; j < 8; j++)
                v[j] = *(const float4*)(h + (size_t)sx[j] * lda + off);
            acc.x += ((v[0].x + v[1].x) + (v[2].x + v[3].x)) + ((v[4].x + v[5].x) + (v[6].x + v[7].x));
            acc.y += ((v[0].y + v[1].y) + (v[2].y + v[3].y)) + ((v[4].y + v[5].y) + (v[6].y + v[7].y));
            acc.z += ((v[0].z + v[1].z) + (v[2].z + v[3].z)) + ((v[4].z + v[5].z) + (v[6].z + v[7].z));
            acc.w += ((v[0].w + v[1].w) + (v[2].w + v[3].w)) + ((v[4].w + v[5].w) + (v[6].w + v[7].w));
        }
        for (; e + 3 < end; e += 4) {
            int s0 = g_csrc[e], s1 = g_csrc[e + 1], s2 = g_csrc[e + 2], s3 = g_csrc[e + 3];
            float4 v0 = *(const float4*)(h + (size_t)s0 * lda + off);
            float4 v1 = *(const float4*)(h + (size_t)s1 * lda + off);
            float4 v2 = *(const float4*)(h + (size_t)s2 * lda + off);
            float4 v3 = *(const float4*)(h + (size_t)s3 * lda + off);
            acc.x += (v0.x + v1.x) + (v2.x + v3.x);
            acc.y += (v0.y + v1.y) + (v2.y + v3.y);
            acc.z += (v0.z + v1.z) + (v2.z + v3.z);
            acc.w += (v0.w + v1.w) + (v2.w + v3.w);
        }
        for (; e < end; e++) {
            int s0 = g_csrc[e];
            float4 v0 = *(const float4*)(h + (size_t)s0 * lda + off);
            acc.x += v0.x; acc.y += v0.y; acc.z += v0.z; acc.w += v0.w;
        }
        // split + store to stage (lane>>2), k-chunk (lane&3)
        float lx0, ly0, lx1, ly1;
        uint32_t h01 = pack_hi(acc.x, acc.y, lx0, ly0);
        uint32_t h23 = pack_hi(acc.z, acc.w, lx1, ly1);
        uint32_t l01 = pack_bf2(lx0, ly0);
        uint32_t l23 = pack_bf2(lx1, ly1);
        const uint32_t aoff = stg * 3072 + (uint32_t)rloc * 48 + aq * 8;
        *(uint32_t*)(dsm + FA_HI + aoff)     = h01;
        *(uint32_t*)(dsm + FA_HI + aoff + 4) = h23;
        *(uint32_t*)(dsm + FA_LO + aoff)     = l01;
        *(uint32_t*)(dsm + FA_LO + aoff + 4) = l23;
    }
    // store W stage 0
    *(uint4*)(dsm + FW + wDst)        = pwh;
    *(uint4*)(dsm + FW + 6144 + wDst) = pwl;
    __syncthreads();

    // ---- phase 2: MMA over 8 resident A stages, W double-buffered ----
    float d[2][4][4];
#pragma unroll
    for (int mt = 0; mt < 2; mt++)
#pragma unroll
        for (int nt = 0; nt < 4; nt++)
#pragma unroll
            for (int i = 0; i < 4; i++) d[mt][nt][i] = 0.f;

    for (int s = 0; s < 8; s++) {
        if (s + 1 < 8) {
            pwh = *(const uint4*)(whptr + (s + 1) * 16);
            pwl = *(const uint4*)(wlptr + (s + 1) * 16);
        }
        const uint32_t aBase = sb + (uint32_t)s * 3072;
        const uint32_t wBase = sb + FW + (uint32_t)(s & 1) * FW_SZ;

        uint32_t ah[2][4], al[2][4], bh2[4][2], bl2[4][2];
#pragma unroll
        for (int mt = 0; mt < 2; mt++) {
            LDMX4(ah[mt], aBase + FA_HI + a_lo + mt * 16 * 48);
            LDMX4(al[mt], aBase + FA_LO + a_lo + mt * 16 * 48);
        }
#pragma unroll
        for (int nt = 0; nt < 4; nt++) {
            LDMX2(bh2[nt], wBase + b_lo + nt * 8 * 48);
            LDMX2(bl2[nt], wBase + 6144 + b_lo + nt * 8 * 48);
        }
#pragma unroll
        for (int mt = 0; mt < 2; mt++)
#pragma unroll
            for (int nt = 0; nt < 4; nt++) {
                mma_bf16(d[mt][nt], al[mt], bh2[nt]);
                mma_bf16(d[mt][nt], ah[mt], bl2[nt]);
                mma_bf16(d[mt][nt], ah[mt], bh2[nt]);
            }

        if (s + 1 < 8) {
            char* wst = dsm + FW + (size_t)((s + 1) & 1) * FW_SZ;
            *(uint4*)(wst + wDst)        = pwh;
            *(uint4*)(wst + 6144 + wDst) = pwl;
            __syncthreads();
        }
    }

    // epilogue: bias + relu, fp32 store
#pragma unroll
    for (int mt = 0; mt < 2; mt++) {
        const int row = row0 + wr * 32 + mt * 16 + (lane >> 2);
#pragma unroll
        for (int nt = 0; nt < 4; nt++) {
            const int col = wc * 32 + nt * 8 + 2 * (lane & 3);
            float2 bb = *(const float2*)(bias + col);
            float2 v0, v1;
            v0.x = fmaxf(d[mt][nt][0] + bb.x, 0.f);
            v0.y = fmaxf(d[mt][nt][1] + bb.y, 0.f);
            v1.x = fmaxf(d[mt][nt][2] + bb.x, 0.f);
            v1.y = fmaxf(d[mt][nt][3] + bb.y, 0.f);
            *(float2*)(C + (size_t)row * ldc + col) = v0;
            *(float2*)(C + (size_t)(row + 8) * ldc + col) = v1;
        }
    }
}

// ================= standard bf16x3 GEMM (K param, head fuse option) ===========
#define ST_AHI 0
#define ST_ALO 3072
#define ST_WHI 6144
#define ST_WLO 12288
#define ST_SZ  18432

__global__ __launch_bounds__(256, 2)
void k_gemm_mma(const float* __restrict__ A, int lda,
                const __nv_bfloat16* __restrict__ Whi,
                const __nv_bfloat16* __restrict__ Wlo,
                const float* __restrict__ bias,
                float* __restrict__ C, int ldc, int K, int doRelu,
                const float* __restrict__ w2h,
                const float* __restrict__ bh,
                float* __restrict__ outv) {
    __shared__ __align__(16) char sm[2][ST_SZ];
    __shared__ float sred[64];

    const int tid = threadIdx.x, warp = tid >> 5, lane = tid & 31;
    const int wr = warp >> 2, wc = warp & 3;
    const int row0 = blockIdx.x * 64;

    const int ar = tid >> 2, aq = tid & 3;
    const int wn = tid >> 1, wh = tid & 1;

    const float* aptr = A + (size_t)(row0 + ar) * lda + 4 * aq;
    const __nv_bfloat16* whptr = Whi + (size_t)wn * K + 8 * wh;
    const __nv_bfloat16* wlptr = Wlo + (size_t)wn * K + 8 * wh;

    const uint32_t sA0 = smem_u32(&sm[0][0]);
    const uint32_t sA1 = smem_u32(&sm[1][0]);

    const uint32_t a_lo = (uint32_t)(((wr * 32) + (lane & 7) + ((lane >> 3) & 1) * 8) * 48
                                     + ((lane >> 4) * 16));
    const uint32_t b_lo = (uint32_t)(((wc * 32) + (lane & 7)) * 48 + ((lane >> 3) & 1) * 16);

    const uint32_t a_st = (uint32_t)(ar * 48 + 8 * aq);
    const uint32_t w_st = (uint32_t)(wn * 48 + 16 * wh);

    if (w2h && tid < 64) sred[tid] = 0.f;

    float d[2][4][4];
#pragma unroll
    for (int mt = 0; mt < 2; mt++)
#pragma unroll
        for (int nt = 0; nt < 4; nt++)
#pragma unroll
            for (int i = 0; i < 4; i++) d[mt][nt][i] = 0.f;

    const int nst = K >> 4;
    float4 a4;
    uint4 wh4, wl4;

    a4 = *(const float4*)aptr;
    wh4 = *(const uint4*)whptr;
    wl4 = *(const uint4*)wlptr;

    {
        char* st = sm[0];
        float lx, ly;
        uint32_t h01 = pack_hi(a4.x, a4.y, lx, ly);
        uint32_t l01 = pack_bf2(lx, ly);
        uint32_t h23 = pack_hi(a4.z, a4.w, lx, ly);
        uint32_t l23 = pack_bf2(lx, ly);
        *(uint32_t*)(st + ST_AHI + a_st) = h01;
        *(uint32_t*)(st + ST_AHI + a_st + 4) = h23;
        *(uint32_t*)(st + ST_ALO + a_st) = l01;
        *(uint32_t*)(st + ST_ALO + a_st + 4) = l23;
        *(uint4*)(st + ST_WHI + w_st) = wh4;
        *(uint4*)(st + ST_WLO + w_st) = wl4;
    }
    __syncthreads();

    for (int s = 0; s < nst; s++) {
        if (s + 1 < nst) {
            a4 = *(const float4*)(aptr + (s + 1) * 16);
            wh4 = *(const uint4*)(whptr + (s + 1) * 16);
            wl4 = *(const uint4*)(wlptr + (s + 1) * 16);
        }
        const uint32_t sbuf = (s & 1) ? sA1 : sA0;

        uint32_t ah[2][4], al[2][4], bh2[4][2], bl2[4][2];
#pragma unroll
        for (int mt = 0; mt < 2; mt++) {
            LDMX4(ah[mt], sbuf + ST_AHI + a_lo + mt * 16 * 48);
            LDMX4(al[mt], sbuf + ST_ALO + a_lo + mt * 16 * 48);
        }
#pragma unroll
        for (int nt = 0; nt < 4; nt++) {
            LDMX2(bh2[nt], sbuf + ST_WHI + b_lo + nt * 8 * 48);
            LDMX2(bl2[nt], sbuf + ST_WLO + b_lo + nt * 8 * 48);
        }
#pragma unroll
        for (int mt = 0; mt < 2; mt++)
#pragma unroll
            for (int nt = 0; nt < 4; nt++) {
                mma_bf16(d[mt][nt], al[mt], bh2[nt]);
                mma_bf16(d[mt][nt], ah[mt], bl2[nt]);
                mma_bf16(d[mt][nt], ah[mt], bh2[nt]);
            }

        if (s + 1 < nst) {
            char* st = sm[(s + 1) & 1];
            float lx, ly;
            uint32_t h01 = pack_hi(a4.x, a4.y, lx, ly);
            uint32_t l01 = pack_bf2(lx, ly);
            uint32_t h23 = pack_hi(a4.z, a4.w, lx, ly);
            uint32_t l23 = pack_bf2(lx, ly);
            *(uint32_t*)(st + ST_AHI + a_st) = h01;
            *(uint32_t*)(st + ST_AHI + a_st + 4) = h23;
            *(uint32_t*)(st + ST_ALO + a_st) = l01;
            *(uint32_t*)(st + ST_ALO + a_st + 4) = l23;
            *(uint4*)(st + ST_WHI + w_st) = wh4;
            *(uint4*)(st + ST_WLO + w_st) = wl4;
            __syncthreads();
        }
    }

#pragma unroll
    for (int mt = 0; mt < 2; mt++) {
        const int row = row0 + wr * 32 + mt * 16 + (lane >> 2);
        float p0 = 0.f, p1 = 0.f;
#pragma unroll
        for (int nt = 0; nt < 4; nt++) {
            const int col = wc * 32 + nt * 8 + 2 * (lane & 3);
            float2 bb = *(const float2*)(bias + col);
            float2 v0, v1;
            v0.x = d[mt][nt][0] + bb.x;
            v0.y = d[mt][nt][1] + bb.y;
            v1.x = d[mt][nt][2] + bb.x;
            v1.y = d[mt][nt][3] + bb.y;
            if (doRelu) {
                v0.x = fmaxf(v0.x, 0.f); v0.y = fmaxf(v0.y, 0.f);
                v1.x = fmaxf(v1.x, 0.f); v1.y = fmaxf(v1.y, 0.f);
            }
            if (w2h) {
                float2 w2 = *(const float2*)(w2h + col);
                p0 += v0.x * w2.x + v0.y * w2.y;
                p1 += v1.x * w2.x + v1.y * w2.y;
            } else {
                *(float2*)(C + (size_t)row * ldc + col) = v0;
                *(float2*)(C + (size_t)(row + 8) * ldc + col) = v1;
            }
        }
        if (w2h) {
            p0 += __shfl_xor_sync(0xffffffffu, p0, 1);
            p0 += __shfl_xor_sync(0xffffffffu, p0, 2);
            p1 += __shfl_xor_sync(0xffffffffu, p1, 1);
            p1 += __shfl_xor_sync(0xffffffffu, p1, 2);
            if ((lane & 3) == 0) {
                const int rl = wr * 32 + mt * 16 + (lane >> 2);
                atomicAdd(&sred[rl], p0);
                atomicAdd(&sred[rl + 8], p1);
            }
        }
    }
    if (w2h) {
        __syncthreads();
        if (tid < 64) outv[row0 + tid] = sred[tid] + bh[0];
    }
}

// ---------------- launch ----------------
extern "C" void kernel_launch(void* const* d_in, const int* in_sizes, int n_in,
                              void* d_out, int out_size) {
    const float* x     = (const float*)d_in[0];
    const int*   ei    = (const int*)d_in[1];
    const float* c0_w1 = (const float*)d_in[2];
    const float* c0_b1 = (const float*)d_in[3];
    const float* c0_w2 = (const float*)d_in[4];
    const float* c0_b2 = (const float*)d_in[5];
    const float* c0_w3 = (const float*)d_in[6];
    const float* c0_b3 = (const float*)d_in[7];
    const float* c1_w1 = (const float*)d_in[8];
    const float* c1_b1 = (const float*)d_in[9];
    const float* c1_w2 = (const float*)d_in[10];
    const float* c1_b2 = (const float*)d_in[11];
    const float* c1_w3 = (const float*)d_in[12];
    const float* c1_b3 = (const float*)d_in[13];
    const float* f_w1  = (const float*)d_in[14];
    const float* f_b1  = (const float*)d_in[15];
    const float* f_w2  = (const float*)d_in[16];
    const float* f_b2  = (const float*)d_in[17];
    float* out = (float*)d_out;

    const int* src = ei;
    const int* dst = ei + N_EDGES;

    float *bufA, *bufCat, *bc0, *bc1;
    __nv_bfloat16 *whi, *wlo;
    cudaGetSymbolAddress((void**)&bufA,   g_bufA);
    cudaGetSymbolAddress((void**)&bufCat, g_bufCat);
    cudaGetSymbolAddress((void**)&whi,    g_whi);
    cudaGetSymbolAddress((void**)&wlo,    g_wlo);
    cudaGetSymbolAddress((void**)&bc0,    g_bc0);
    cudaGetSymbolAddress((void**)&bc1,    g_bc1);

    cudaFuncSetAttribute(k_spgemm, cudaFuncAttributeMaxDynamicSharedMemorySize, F_SMEM);

    const int TB = 256;
    const dim3 gEdges((N_EDGES + TB - 1) / TB);                // 2500
    const dim3 gGemm(N_NODES / 64);                            // 625
    const dim3 gWsplit((N_NODES + 255) / 256);                 // 157

    k_wsplit<<<gWsplit, 256>>>(c0_w2, c1_w2);                  // + zero g_cnt
    k_combo<<<256, 256>>>(c1_w1, c0_w3, c0_b3, c1_b1, f_w1, c1_w3, c1_b3, f_b1);
    k_lin_hist<<<5000, TB>>>(x, c0_w1, c0_b1, bufA, dst);
    k_scan1<<<SCAN_BLOCKS, 1024>>>();
    k_scan23<<<SCAN_BLOCKS, 1024>>>();
    k_fill<<<gEdges, TB>>>(src, dst);

    // conv0 (fused spmm+gemm for both levels)
    k_spgemm<<<gGemm, TB, F_SMEM>>>(bufA, HID, whi + WOFF_C0W2, wlo + WOFF_C0W2,
                                    c0_b2, bufCat, 2 * HID);
    k_spgemm<<<gGemm, TB, F_SMEM>>>(bufCat, 2 * HID, whi + WOFF_C0W2, wlo + WOFF_C0W2,
                                    c0_b2, bufCat + HID, 2 * HID);
    k_gemm_mma<<<gGemm, TB>>>(bufCat, 2 * HID, whi + WOFF_CB0, wlo + WOFF_CB0, bc0,
                              bufA, HID, 2 * HID, 1, nullptr, nullptr, nullptr);

    // conv1
    k_spgemm<<<gGemm, TB, F_SMEM>>>(bufA, HID, whi + WOFF_C1W2, wlo + WOFF_C1W2,
                                    c1_b2, bufCat, 2 * HID);
    k_spgemm<<<gGemm, TB, F_SMEM>>>(bufCat, 2 * HID, whi + WOFF_C1W2, wlo + WOFF_C1W2,
                                    c1_b2, bufCat + HID, 2 * HID);
    // fused lin3(conv1) + f_w1 + relu + head -> out
    k_gemm_mma<<<gGemm, TB>>>(bufCat, 2 * HID, whi + WOFF_CB1, wlo + WOFF_CB1, bc1,
                              nullptr, HID, 2 * HID, 1, f_w2, f_b2, out);
}

// round 15
// speedup vs baseline: 1.1210x; 1.1210x over previous
#include <cuda_runtime.h>
#include <cuda_bf16.h>
#include <cstdint>

#define N_NODES 40000
#define N_EDGES 640000
#define HID 128
#define SCAN_BLOCKS 40   // 40 * 1024 = 40960 >= N_NODES

// ---------------- scratch (static __device__, no allocations) ----------------
__device__ float g_bufA  [N_NODES * HID];
__device__ float g_bufAgg[N_NODES * HID];
__device__ float g_bufCat[N_NODES * 2 * HID];
__device__ int   g_cnt   [N_NODES];
__device__ int   g_rp    [N_NODES + 1];
__device__ int   g_cursor[N_NODES];
__device__ int   g_csrc  [N_EDGES];
__device__ int   g_bsum  [SCAN_BLOCKS];
// pre-split weights (bf16 hi/lo): c0w2, c1w2, combo0, combo1
#define WOFF_C0W2 0
#define WOFF_C1W2 16384
#define WOFF_CB0  32768
#define WOFF_CB1  65536
#define WTOTAL    98304
__device__ __nv_bfloat16 g_whi[WTOTAL];
__device__ __nv_bfloat16 g_wlo[WTOTAL];
__device__ float g_bc0[HID];   // combo0 bias = c1_w1 @ c0_b3 + c1_b1
__device__ float g_bc1[HID];   // combo1 bias = f_w1 @ c1_b3 + f_b1

// ---------------- fused: lin_in (blocks 0..2499) + hist (blocks 2500..4999) ---
__global__ __launch_bounds__(256)
void k_lin_hist(const float* __restrict__ x, const float* __restrict__ w1,
                const float* __restrict__ b1, float* __restrict__ out,
                const int* __restrict__ dst) {
    if (blockIdx.x < 2500) {
        __shared__ float xs[16 * 11];
        const int tid = threadIdx.x;
        const int col = tid & 127, half = tid >> 7;
        float wr[11];
#pragma unroll
        for (int k = 0; k < 11; k++) wr[k] = w1[col * 11 + k];
        const float bb = b1[col];
        const int row0 = blockIdx.x * 16;
        for (int i = tid; i < 16 * 11; i += 256) xs[i] = x[row0 * 11 + i];
        __syncthreads();
#pragma unroll
        for (int rr = 0; rr < 8; rr++) {
            const int r = half * 8 + rr;
            float acc = bb;
#pragma unroll
            for (int k = 0; k < 11; k++) acc += xs[r * 11 + k] * wr[k];
            out[(size_t)(row0 + r) * HID + col] = fmaxf(acc, 0.f);
        }
    } else {
        int e = (blockIdx.x - 2500) * 256 + threadIdx.x;
        if (e < N_EDGES) atomicAdd(&g_cnt[dst[e]], 1);
    }
}

// ---------------- 2-phase parallel scan ----------------
__global__ __launch_bounds__(1024)
void k_scan1() {
    __shared__ int warpsum[32];
    const int tid = threadIdx.x;
    const int lane = tid & 31, wid = tid >> 5;
    const int i = blockIdx.x * 1024 + tid;
    int v = (i < N_NODES) ? g_cnt[i] : 0;
    int s = v;
#pragma unroll
    for (int o = 1; o < 32; o <<= 1) {
        int t = __shfl_up_sync(0xffffffffu, s, o);
        if (lane >= o) s += t;
    }
    if (lane == 31) warpsum[wid] = s;
    __syncthreads();
    if (wid == 0) {
        int w = warpsum[lane];
#pragma unroll
        for (int o = 1; o < 32; o <<= 1) {
            int t = __shfl_up_sync(0xffffffffu, w, o);
            if (lane >= o) w += t;
        }
        warpsum[lane] = w;
    }
    __syncthreads();
    int incl = s + (wid ? warpsum[wid - 1] : 0);
    if (i < N_NODES) g_rp[i] = incl - v;       // block-local exclusive
    if (tid == 1023) g_bsum[blockIdx.x] = incl; // block total
}

// each block redundantly scans the 40 block sums, then applies its offset
__global__ __launch_bounds__(1024)
void k_scan23() {
    __shared__ int boff;
    __shared__ int total;
    if (threadIdx.x == 0) {
        int run = 0, mine = 0;
        for (int b = 0; b < SCAN_BLOCKS; b++) {
            if (b == (int)blockIdx.x) mine = run;
            run += g_bsum[b];
        }
        boff = mine;
        total = run;
    }
    __syncthreads();
    const int i = blockIdx.x * 1024 + threadIdx.x;
    if (i < N_NODES) {
        int v = g_rp[i] + boff;
        g_rp[i] = v;
        g_cursor[i] = v;
    }
    if (blockIdx.x == 0 && threadIdx.x == 0) g_rp[N_NODES] = total;
}

__global__ void k_fill(const int* __restrict__ src, const int* __restrict__ dst) {
    int e = blockIdx.x * blockDim.x + threadIdx.x;
    if (e < N_EDGES) {
        int p = atomicAdd(&g_cursor[dst[e]], 1);
        g_csrc[p] = src[e];
    }
}

// ---------------- SpMM ----------------
__global__ void k_spmm(const float* __restrict__ h, int lda, float* __restrict__ agg) {
    const int gw = (blockIdx.x * blockDim.x + threadIdx.x) >> 5;
    const int lane = threadIdx.x & 31;
    if (gw >= N_NODES) return;
    const int beg = g_rp[gw], end = g_rp[gw + 1];
    const int off = lane << 2;
    float4 acc = make_float4(0.f, 0.f, 0.f, 0.f);
    int e = beg;
    for (; e + 7 < end; e += 8) {
        int sx[8];
#pragma unroll
        for (int j = 0; j < 8; j++) sx[j] = g_csrc[e + j];
        float4 v[8];
#pragma unroll
        for (int j = 0; j < 8; j++)
            v[j] = *(const float4*)(h + (size_t)sx[j] * lda + off);
        acc.x += ((v[0].x + v[1].x) + (v[2].x + v[3].x)) + ((v[4].x + v[5].x) + (v[6].x + v[7].x));
        acc.y += ((v[0].y + v[1].y) + (v[2].y + v[3].y)) + ((v[4].y + v[5].y) + (v[6].y + v[7].y));
        acc.z += ((v[0].z + v[1].z) + (v[2].z + v[3].z)) + ((v[4].z + v[5].z) + (v[6].z + v[7].z));
        acc.w += ((v[0].w + v[1].w) + (v[2].w + v[3].w)) + ((v[4].w + v[5].w) + (v[6].w + v[7].w));
    }
    for (; e + 3 < end; e += 4) {
        int s0 = g_csrc[e], s1 = g_csrc[e + 1], s2 = g_csrc[e + 2], s3 = g_csrc[e + 3];
        float4 v0 = *(const float4*)(h + (size_t)s0 * lda + off);
        float4 v1 = *(const float4*)(h + (size_t)s1 * lda + off);
        float4 v2 = *(const float4*)(h + (size_t)s2 * lda + off);
        float4 v3 = *(const float4*)(h + (size_t)s3 * lda + off);
        acc.x += (v0.x + v1.x) + (v2.x + v3.x);
        acc.y += (v0.y + v1.y) + (v2.y + v3.y);
        acc.z += (v0.z + v1.z) + (v2.z + v3.z);
        acc.w += (v0.w + v1.w) + (v2.w + v3.w);
    }
    for (; e < end; e++) {
        int s0 = g_csrc[e];
        float4 v0 = *(const float4*)(h + (size_t)s0 * lda + off);
        acc.x += v0.x; acc.y += v0.y; acc.z += v0.z; acc.w += v0.w;
    }
    *(float4*)(agg + (size_t)gw * HID + off) = acc;
}

// ---------------- weight pre-split for c0w2/c1w2 (+ g_cnt zeroing) ------------
__global__ void k_wsplit(const float* __restrict__ s0, const float* __restrict__ s1) {
    int i = blockIdx.x * 256 + threadIdx.x;
    if (i < N_NODES) g_cnt[i] = 0;
    if (i >= 32768) return;
    float v = (i < 16384) ? s0[i] : s1[i - 16384];
    __nv_bfloat16 h = __float2bfloat16_rn(v);
    g_whi[i] = h;
    g_wlo[i] = __float2bfloat16_rn(v - __bfloat162float(h));
}

// ---------------- combo precompute: combo = w1[128,128] @ w3[128,256] ---------
__global__ __launch_bounds__(256)
void k_combo(const float* __restrict__ c1w1, const float* __restrict__ c0w3,
             const float* __restrict__ c0b3, const float* __restrict__ c1b1,
             const float* __restrict__ fw1,  const float* __restrict__ c1w3,
             const float* __restrict__ c1b3, const float* __restrict__ fb1) {
    __shared__ float wrow[128];
    const int c = blockIdx.x >> 7;
    const int i = blockIdx.x & 127;
    const int j = threadIdx.x;
    const float* w1 = c ? fw1 : c1w1;
    const float* w3 = c ? c1w3 : c0w3;
    const float* b3 = c ? c1b3 : c0b3;
    const float* b1 = c ? fb1 : c1b1;
    if (j < 128) wrow[j] = w1[i * 128 + j];
    __syncthreads();
    float acc = 0.f;
#pragma unroll 8
    for (int k = 0; k < 128; k++) acc += wrow[k] * w3[k * 256 + j];
    const int off = (c ? WOFF_CB1 : WOFF_CB0) + i * 256 + j;
    __nv_bfloat16 h = __float2bfloat16_rn(acc);
    g_whi[off] = h;
    g_wlo[off] = __float2bfloat16_rn(acc - __bfloat162float(h));
    if (j == 0) {
        float s = 0.f;
        for (int k = 0; k < 128; k++) s += wrow[k] * b3[k];
        (c ? g_bc1 : g_bc0)[i] = s + b1[i];
    }
}

// ================= mma.sync bf16x3 GEMM (R5 inner loop, head fuse) ============
__device__ __forceinline__ uint32_t smem_u32(const void* p) {
    uint32_t a;
    asm("{ .reg .u64 t; cvta.to.shared.u64 t, %1; cvt.u32.u64 %0, t; }"
        : "=r"(a) : "l"(p));
    return a;
}
__device__ __forceinline__ void mma_bf16(float d[4], const uint32_t a[4],
                                         const uint32_t b[2]) {
    asm volatile(
        "mma.sync.aligned.m16n8k16.row.col.f32.bf16.bf16.f32 "
        "{%0,%1,%2,%3}, {%4,%5,%6,%7}, {%8,%9}, {%0,%1,%2,%3};"
        : "+f"(d[0]), "+f"(d[1]), "+f"(d[2]), "+f"(d[3])
        : "r"(a[0]), "r"(a[1]), "r"(a[2]), "r"(a[3]), "r"(b[0]), "r"(b[1]));
}
#define LDMX4(r, addr) \
    asm volatile("ldmatrix.sync.aligned.m8n8.x4.shared.b16 {%0,%1,%2,%3}, [%4];" \
                 : "=r"((r)[0]), "=r"((r)[1]), "=r"((r)[2]), "=r"((r)[3]) : "r"(addr))
#define LDMX2(r, addr) \
    asm volatile("ldmatrix.sync.aligned.m8n8.x2.shared.b16 {%0,%1}, [%2];" \
                 : "=r"((r)[0]), "=r"((r)[1]) : "r"(addr))

__device__ __forceinline__ uint32_t pack_hi(float x, float y, float& lx, float& ly) {
    __nv_bfloat162 h = __floats2bfloat162_rn(x, y);
    lx = x - __bfloat162float(h.x);
    ly = y - __bfloat162float(h.y);
    return *(uint32_t*)&h;
}
__device__ __forceinline__ uint32_t pack_bf2(float x, float y) {
    __nv_bfloat162 h = __floats2bfloat162_rn(x, y);
    return *(uint32_t*)&h;
}

#define ST_AHI 0
#define ST_ALO 3072
#define ST_WHI 6144
#define ST_WLO 12288
#define ST_SZ  18432

__global__ __launch_bounds__(256, 2)
void k_gemm_mma(const float* __restrict__ A, int lda,
                const __nv_bfloat16* __restrict__ Whi,
                const __nv_bfloat16* __restrict__ Wlo,
                const float* __restrict__ bias,
                float* __restrict__ C, int ldc, int K, int doRelu,
                const float* __restrict__ w2h,   // head weight [128] (nullable)
                const float* __restrict__ bh,    // head bias [1]
                float* __restrict__ outv) {      // head out [N]
    __shared__ __align__(16) char sm[2][ST_SZ];
    __shared__ float sred[64];

    const int tid = threadIdx.x, warp = tid >> 5, lane = tid & 31;
    const int wr = warp >> 2, wc = warp & 3;
    const int row0 = blockIdx.x * 64;

    const int ar = tid >> 2, aq = tid & 3;
    const int wn = tid >> 1, wh = tid & 1;

    const float* aptr = A + (size_t)(row0 + ar) * lda + 4 * aq;
    const __nv_bfloat16* whptr = Whi + (size_t)wn * K + 8 * wh;
    const __nv_bfloat16* wlptr = Wlo + (size_t)wn * K + 8 * wh;

    const uint32_t sA0 = smem_u32(&sm[0][0]);
    const uint32_t sA1 = smem_u32(&sm[1][0]);

    const uint32_t a_lo = (uint32_t)(((wr * 32) + (lane & 7) + ((lane >> 3) & 1) * 8) * 48
                                     + ((lane >> 4) * 16));
    const uint32_t b_lo = (uint32_t)(((wc * 32) + (lane & 7)) * 48 + ((lane >> 3) & 1) * 16);

    const uint32_t a_st = (uint32_t)(ar * 48 + 8 * aq);
    const uint32_t w_st = (uint32_t)(wn * 48 + 16 * wh);

    if (w2h && tid < 64) sred[tid] = 0.f;

    float d[2][4][4];
#pragma unroll
    for (int mt = 0; mt < 2; mt++)
#pragma unroll
        for (int nt = 0; nt < 4; nt++)
#pragma unroll
            for (int i = 0; i < 4; i++) d[mt][nt][i] = 0.f;

    const int nst = K >> 4;
    float4 a4;
    uint4 wh4, wl4;

    a4 = *(const float4*)aptr;
    wh4 = *(const uint4*)whptr;
    wl4 = *(const uint4*)wlptr;

    {
        char* st = sm[0];
        float lx, ly;
        uint32_t h01 = pack_hi(a4.x, a4.y, lx, ly);
        uint32_t l01 = pack_bf2(lx, ly);
        uint32_t h23 = pack_hi(a4.z, a4.w, lx, ly);
        uint32_t l23 = pack_bf2(lx, ly);
        *(uint32_t*)(st + ST_AHI + a_st) = h01;
        *(uint32_t*)(st + ST_AHI + a_st + 4) = h23;
        *(uint32_t*)(st + ST_ALO + a_st) = l01;
        *(uint32_t*)(st + ST_ALO + a_st + 4) = l23;
        *(uint4*)(st + ST_WHI + w_st) = wh4;
        *(uint4*)(st + ST_WLO + w_st) = wl4;
    }
    __syncthreads();

    for (int s = 0; s < nst; s++) {
        if (s + 1 < nst) {
            a4 = *(const float4*)(aptr + (s + 1) * 16);
            wh4 = *(const uint4*)(whptr + (s + 1) * 16);
            wl4 = *(const uint4*)(wlptr + (s + 1) * 16);
        }
        const uint32_t sb = (s & 1) ? sA1 : sA0;

        uint32_t ah[2][4], al[2][4], bh2[4][2], bl2[4][2];
#pragma unroll
        for (int mt = 0; mt < 2; mt++) {
            LDMX4(ah[mt], sb + ST_AHI + a_lo + mt * 16 * 48);
            LDMX4(al[mt], sb + ST_ALO + a_lo + mt * 16 * 48);
        }
#pragma unroll
        for (int nt = 0; nt < 4; nt++) {
            LDMX2(bh2[nt], sb + ST_WHI + b_lo + nt * 8 * 48);
            LDMX2(bl2[nt], sb + ST_WLO + b_lo + nt * 8 * 48);
        }
#pragma unroll
        for (int mt = 0; mt < 2; mt++)
#pragma unroll
            for (int nt = 0; nt < 4; nt++) {
                mma_bf16(d[mt][nt], al[mt], bh2[nt]);
                mma_bf16(d[mt][nt], ah[mt], bl2[nt]);
                mma_bf16(d[mt][nt], ah[mt], bh2[nt]);
            }

        if (s + 1 < nst) {
            char* st = sm[(s + 1) & 1];
            float lx, ly;
            uint32_t h01 = pack_hi(a4.x, a4.y, lx, ly);
            uint32_t l01 = pack_bf2(lx, ly);
            uint32_t h23 = pack_hi(a4.z, a4.w, lx, ly);
            uint32_t l23 = pack_bf2(lx, ly);
            *(uint32_t*)(st + ST_AHI + a_st) = h01;
            *(uint32_t*)(st + ST_AHI + a_st + 4) = h23;
            *(uint32_t*)(st + ST_ALO + a_st) = l01;
            *(uint32_t*)(st + ST_ALO + a_st + 4) = l23;
            *(uint4*)(st + ST_WHI + w_st) = wh4;
            *(uint4*)(st + ST_WLO + w_st) = wl4;
            __syncthreads();
        }
    }

#pragma unroll
    for (int mt = 0; mt < 2; mt++) {
        const int row = row0 + wr * 32 + mt * 16 + (lane >> 2);
        float p0 = 0.f, p1 = 0.f;
#pragma unroll
        for (int nt = 0; nt < 4; nt++) {
            const int col = wc * 32 + nt * 8 + 2 * (lane & 3);
            float2 bb = *(const float2*)(bias + col);
            float2 v0, v1;
            v0.x = d[mt][nt][0] + bb.x;
            v0.y = d[mt][nt][1] + bb.y;
            v1.x = d[mt][nt][2] + bb.x;
            v1.y = d[mt][nt][3] + bb.y;
            if (doRelu) {
                v0.x = fmaxf(v0.x, 0.f); v0.y = fmaxf(v0.y, 0.f);
                v1.x = fmaxf(v1.x, 0.f); v1.y = fmaxf(v1.y, 0.f);
            }
            if (w2h) {
                float2 w2 = *(const float2*)(w2h + col);
                p0 += v0.x * w2.x + v0.y * w2.y;
                p1 += v1.x * w2.x + v1.y * w2.y;
            } else {
                *(float2*)(C + (size_t)row * ldc + col) = v0;
                *(float2*)(C + (size_t)(row + 8) * ldc + col) = v1;
            }
        }
        if (w2h) {
            p0 += __shfl_xor_sync(0xffffffffu, p0, 1);
            p0 += __shfl_xor_sync(0xffffffffu, p0, 2);
            p1 += __shfl_xor_sync(0xffffffffu, p1, 1);
            p1 += __shfl_xor_sync(0xffffffffu, p1, 2);
            if ((lane & 3) == 0) {
                const int rl = wr * 32 + mt * 16 + (lane >> 2);
                atomicAdd(&sred[rl], p0);
                atomicAdd(&sred[rl + 8], p1);
            }
        }
    }
    if (w2h) {
        __syncthreads();
        if (tid < 64) outv[row0 + tid] = sred[tid] + bh[0];
    }
}

// ---------------- launch ----------------
extern "C" void kernel_launch(void* const* d_in, const int* in_sizes, int n_in,
                              void* d_out, int out_size) {
    const float* x     = (const float*)d_in[0];
    const int*   ei    = (const int*)d_in[1];
    const float* c0_w1 = (const float*)d_in[2];
    const float* c0_b1 = (const float*)d_in[3];
    const float* c0_w2 = (const float*)d_in[4];
    const float* c0_b2 = (const float*)d_in[5];
    const float* c0_w3 = (const float*)d_in[6];
    const float* c0_b3 = (const float*)d_in[7];
    const float* c1_w1 = (const float*)d_in[8];
    const float* c1_b1 = (const float*)d_in[9];
    const float* c1_w2 = (const float*)d_in[10];
    const float* c1_b2 = (const float*)d_in[11];
    const float* c1_w3 = (const float*)d_in[12];
    const float* c1_b3 = (const float*)d_in[13];
    const float* f_w1  = (const float*)d_in[14];
    const float* f_b1  = (const float*)d_in[15];
    const float* f_w2  = (const float*)d_in[16];
    const float* f_b2  = (const float*)d_in[17];
    float* out = (float*)d_out;

    const int* src = ei;
    const int* dst = ei + N_EDGES;

    float *bufA, *bufAgg, *bufCat, *bc0, *bc1;
    __nv_bfloat16 *whi, *wlo;
    cudaGetSymbolAddress((void**)&bufA,   g_bufA);
    cudaGetSymbolAddress((void**)&bufAgg, g_bufAgg);
    cudaGetSymbolAddress((void**)&bufCat, g_bufCat);
    cudaGetSymbolAddress((void**)&whi,    g_whi);
    cudaGetSymbolAddress((void**)&wlo,    g_wlo);
    cudaGetSymbolAddress((void**)&bc0,    g_bc0);
    cudaGetSymbolAddress((void**)&bc1,    g_bc1);

    const int TB = 256;
    const dim3 gEdges((N_EDGES + TB - 1) / TB);                // 2500
    const dim3 gWarpPerNode((N_NODES * 32 + TB - 1) / TB);     // 5000
    const dim3 gGemm(N_NODES / 64);                            // 625
    const dim3 gWsplit((N_NODES + 255) / 256);                 // 157

    k_wsplit<<<gWsplit, 256>>>(c0_w2, c1_w2);                  // + zero g_cnt
    k_combo<<<256, 256>>>(c1_w1, c0_w3, c0_b3, c1_b1, f_w1, c1_w3, c1_b3, f_b1);
    k_lin_hist<<<5000, TB>>>(x, c0_w1, c0_b1, bufA, dst);
    k_scan1<<<SCAN_BLOCKS, 1024>>>();
    k_scan23<<<SCAN_BLOCKS, 1024>>>();
    k_fill<<<gEdges, TB>>>(src, dst);

    // conv0
    k_spmm<<<gWarpPerNode, TB>>>(bufA, HID, bufAgg);
    k_gemm_mma<<<gGemm, TB>>>(bufAgg, HID, whi + WOFF_C0W2, wlo + WOFF_C0W2, c0_b2,
                              bufCat, 2 * HID, HID, 1, nullptr, nullptr, nullptr);
    k_spmm<<<gWarpPerNode, TB>>>(bufCat, 2 * HID, bufAgg);
    k_gemm_mma<<<gGemm, TB>>>(bufAgg, HID, whi + WOFF_C0W2, wlo + WOFF_C0W2, c0_b2,
                              bufCat + HID, 2 * HID, HID, 1, nullptr, nullptr, nullptr);
    k_gemm_mma<<<gGemm, TB>>>(bufCat, 2 * HID, whi + WOFF_CB0, wlo + WOFF_CB0, bc0,
                              bufA, HID, 2 * HID, 1, nullptr, nullptr, nullptr);

    // conv1
    k_spmm<<<gWarpPerNode, TB>>>(bufA, HID, bufAgg);
    k_gemm_mma<<<gGemm, TB>>>(bufAgg, HID, whi + WOFF_C1W2, wlo + WOFF_C1W2, c1_b2,
                              bufCat, 2 * HID, HID, 1, nullptr, nullptr, nullptr);
    k_spmm<<<gWarpPerNode, TB>>>(bufCat, 2 * HID, bufAgg);
    k_gemm_mma<<<gGemm, TB>>>(bufAgg, HID, whi + WOFF_C1W2, wlo + WOFF_C1W2, c1_b2,
                              bufCat + HID, 2 * HID, HID, 1, nullptr, nullptr, nullptr);
    // fused lin3(conv1) + f_w1 + relu + head -> out
    k_gemm_mma<<<gGemm, TB>>>(bufCat, 2 * HID, whi + WOFF_CB1, wlo + WOFF_CB1, bc1,
                              nullptr, HID, 2 * HID, 1, f_w2, f_b2, out);
}